// round 14
// baseline (speedup 1.0000x reference)
#include <cuda_runtime.h>

#define BB 4
#define CC 256
#define HH 256
#define WW 256
#define HWSZ (HH * WW)
#define NPIX (BB * HWSZ)
#define FULLMASK 0xFFFFFFFFu

// iv float plane: row stride 272 floats (68 float4), plane col = image col + 4
// plane rows: 0,1 zero | 2..257 = image rows 0..255 | 258..295 zero
#define SPF 272
#define SPF4 68
#define PROWS 296
#define PLSZF (PROWS * SPF)
#define PLSZF4 (PROWS * SPF4)
// fv byte plane: row stride 272 bytes, plane col = image col + 8
#define SPB 272
#define PLSZB (PROWS * SPB)
#define PLSZB16 (PLSZB / 16)           // 5032 uint4 per batch

// phase-2: 8 hbands x 32 rows, 4 batches, 256 channels
#define HBANDS 8
#define HROWS 32
#define NTASK2 (HBANDS * 4 * 256)      // 8192 warp-tasks
#define NBLKC (NTASK2 / 8)             // 1024 blocks

__device__ uint4 g_fvb4[BB * PLSZB16];     // int8 fv: +-1 correct (sign=class), 0 else
__device__ float4 g_ivp4[BB * PLSZF4];     // iv: +-1/(cnt+1e-5) if mse-masked else 0
__device__ unsigned char g_info[NPIX];
__device__ double g_loss[2];
__device__ int g_nsel[2], g_cal[2];

// ---------------- Kernel A: zero planes + per-pixel info -------------------
__global__ void kernA(const int* __restrict__ gt, const float* __restrict__ clf) {
    int p = blockIdx.x * blockDim.x + threadIdx.x;
    const uint4 zi = make_uint4(0, 0, 0, 0);
    const float4 zf = make_float4(0.f, 0.f, 0.f, 0.f);
    for (int i = p; i < BB * PLSZB16; i += NPIX) g_fvb4[i] = zi;
    for (int i = p; i < BB * PLSZF4; i += NPIX) g_ivp4[i] = zf;
    if (p == 0) {
        g_loss[0] = 0.0; g_loss[1] = 0.0;
        g_nsel[0] = 0; g_nsel[1] = 0;
        g_cal[0] = 0; g_cal[1] = 0;
    }
    int b = p >> 16;
    int hw = p & (HWSZ - 1);
    int h = hw >> 8;
    int w = hw & (WW - 1);
    int g = gt[p];
    float c0 = clf[(size_t)(b * 2) * HWSZ + hw];
    float c1 = clf[(size_t)(b * 2 + 1) * HWSZ + hw];
    int pred = (c1 > c0) ? 1 : 0;              // argmax ties -> index 0
    int correct = (pred == g) ? 1 : 0;
    int edge = (g == -1) ? 1 : 0;
    if (h < HH - 5) edge |= (gt[p + 5 * WW] != g) ? 1 : 0;
    if (w < WW - 5) edge |= (gt[p + 5] != g) ? 1 : 0;
    g_info[p] = (unsigned char)((g & 1) | (correct << 1) | (edge << 2));
}

// ---------------- Kernel B: ring counts -> fv/iv planes + counters ---------
__global__ void kernB() {
    int p = blockIdx.x * blockDim.x + threadIdx.x;
    int hw = p & (HWSZ - 1);
    int h = hw >> 8;
    int w = hw & (WW - 1);
    int b = p >> 16;
    unsigned info = g_info[p];
    int g = info & 1;
    int correct = (info >> 1) & 1;
    int edge = (info >> 2) & 1;
    int cntCorr = 0, cntCls = 0;
#pragma unroll
    for (int dh = -2; dh <= 2; dh++) {
#pragma unroll
        for (int dw = -2; dw <= 2; dw++) {
            if (dh == 0 && dw == 0) continue;
            int hh = h + dh, wp = w + dw;
            if ((unsigned)hh < HH && (unsigned)wp < WW) {
                unsigned qi = g_info[p + dh * WW + dw];
                int same = ((int)(qi & 1) == g) ? 1 : 0;
                cntCls += same;
                cntCorr += same & (int)((qi >> 1) & 1);
            }
        }
    }
    int mse = correct & edge & (cntCorr >= 1 ? 1 : 0);
    int cal = edge & (cntCls >= 1 ? 1 : 0);

    signed char fvb = correct ? (g ? 1 : -1) : 0;
    float inv = 1.0f / ((float)cntCorr + 1e-5f);
    float ivs = mse ? (g ? inv : -inv) : 0.0f;

    ((signed char*)g_fvb4)[(size_t)b * PLSZB + (h + 2) * SPB + (w + 8)] = fvb;
    ((float*)g_ivp4)[(size_t)b * PLSZF + (h + 2) * SPF + (w + 4)] = ivs;

    unsigned bm;
    bm = __ballot_sync(FULLMASK, mse && g == 0);
    if ((threadIdx.x & 31) == 0 && bm) atomicAdd(&g_nsel[0], __popc(bm));
    bm = __ballot_sync(FULLMASK, mse && g == 1);
    if ((threadIdx.x & 31) == 0 && bm) atomicAdd(&g_nsel[1], __popc(bm));
    bm = __ballot_sync(FULLMASK, cal && g == 0);
    if ((threadIdx.x & 31) == 0 && bm) atomicAdd(&g_cal[0], __popc(bm));
    bm = __ballot_sync(FULLMASK, cal && g == 1);
    if ((threadIdx.x & 31) == 0 && bm) atomicAdd(&g_cal[1], __popc(bm));
}

// decode 4 signed bytes of w -> floats (dp4a byte extract, sign-extended)
__device__ __forceinline__ float4 dec4(unsigned w) {
    int b0, b1, b2, b3;
    asm("dp4a.s32.s32 %0, %1, %2, %3;" : "=r"(b0) : "r"(w), "r"(0x00000001), "r"(0));
    asm("dp4a.s32.s32 %0, %1, %2, %3;" : "=r"(b1) : "r"(w), "r"(0x00000100), "r"(0));
    asm("dp4a.s32.s32 %0, %1, %2, %3;" : "=r"(b2) : "r"(w), "r"(0x00010000), "r"(0));
    asm("dp4a.s32.s32 %0, %1, %2, %3;" : "=r"(b3) : "r"(w), "r"(0x01000000), "r"(0));
    return make_float4(__int2float_rn(b0), __int2float_rn(b1),
                       __int2float_rn(b2), __int2float_rn(b3));
}

// u += x*f^2, v += x*f (per element)
__device__ __forceinline__ void accum4(const float4 xv, const float4 fv,
                                       float4& u, float4& v) {
    float s;
    s = xv.x * fv.x; v.x += s; u.x = fmaf(s, fv.x, u.x);
    s = xv.y * fv.y; v.y += s; u.y = fmaf(s, fv.y, u.y);
    s = xv.z * fv.z; v.z += s; u.z = fmaf(s, fv.z, u.z);
    s = xv.w * fv.w; v.w += s; u.w = fmaf(s, fv.w, u.w);
}
__device__ __forceinline__ void decum4(const float4 xv, const float4 fv,
                                       float4& u, float4& v) {
    float s;
    s = xv.x * fv.x; v.x -= s; u.x = fmaf(-s, fv.x, u.x);
    s = xv.y * fv.y; v.y -= s; u.y = fmaf(-s, fv.y, u.y);
    s = xv.z * fv.z; v.z -= s; u.z = fmaf(-s, fv.z, u.z);
    s = xv.w * fv.w; v.w -= s; u.w = fmaf(-s, fv.w, u.w);
}

// 8 sliding 5-wide window sums via prefix differences
__device__ __forceinline__ void win8(float el0, float el1, const float4 A,
                                     const float4 B, float er0, float er1,
                                     float* W) {
    float pm1 = el0 + el1;
    float q0 = pm1 + A.x;
    float q1 = q0 + A.y;
    float q2 = q1 + A.z;
    float q3 = q2 + A.w;
    float q4 = q3 + B.x;
    float q5 = q4 + B.y;
    float q6 = q5 + B.z;
    float q7 = q6 + B.w;
    float q8 = q7 + er0;
    float q9 = q8 + er1;
    W[0] = q2;
    W[1] = q3 - el0;
    W[2] = q4 - pm1;
    W[3] = q5 - q0;
    W[4] = q6 - q1;
    W[5] = q7 - q2;
    W[6] = q8 - q3;
    W[7] = q9 - q4;
}

// loss term: class = sign(s); dd = cen + |s|*(cen - U/2) - s*V/2
__device__ __forceinline__ void epi(float s, float U, float V, float cen,
                                    float& a0, float& a1) {
    float a = fabsf(s);
    float t1 = fmaf(-0.5f, U, cen);
    float dd = fmaf(a, t1, cen);
    dd = fmaf(-0.5f * s, V, dd);
    float q = dd * dd;
    if (s > 0.f) a1 += q; else if (s < 0.f) a0 += q;
}

// ---------------- Kernel C: span-8, center ring-2, int8 fv -----------------
// Warp-task = (hband, b, ch): 32 output rows x 256 cols. Lane owns image cols
// 8*lane..8*lane+7 -> one warp = full row; warp-edge halo IS the image
// boundary (zeroed selects). u = 5-row col sums of x*f^2, v = of x*f.
// Slide: add row r+2, window, subtract row r-2 (x reloaded from L1-hot line,
// fv byte plane), epilogue at center r (x from 2-deep parity ring).
// Per row: 2 LDG.128 x-in + 2 LDG.64 fv + 2 LDG.128 iv + 2 LDG.128 x-dep
// + 8 shuffles serve 256 px.
__global__ void __launch_bounds__(256, 3) kernC(const float* __restrict__ x) {
    __shared__ double sred[2][8];
    const int lane = threadIdx.x & 31;
    const int wid = threadIdx.x >> 5;
    const int tw = blockIdx.x * 8 + wid;
    const int hb = tw & (HBANDS - 1);
    const int b = (tw >> 3) & 3;
    const int ch = tw >> 5;
    const int h0 = hb * HROWS;             // multiple of 32 (even)
    const float4 z4 = make_float4(0.f, 0.f, 0.f, 0.f);

    const float* xp = x + ((size_t)(b * CC + ch) << 16) + (lane << 3);
    const signed char* fb = (const signed char*)g_fvb4 + (size_t)b * PLSZB + 8 + (lane << 3);
    const float4* pi = g_ivp4 + (size_t)b * PLSZF4 + (lane << 1) + 1;

    float4 rcA[2], rcB[2];                 // center ring, slot = row & 1
    float4 uA = z4, uB = z4, vA = z4, vB = z4;

    // prologue: image rows h0-2..h0+1, fv plane rows h0..h0+3
#pragma unroll
    for (int j = 0; j < 4; j++) {
        int rr = h0 - 2 + j;
        int rc = rr < 0 ? 0 : rr;
        const float* xr = xp + (rc << 8);
        float4 xa = __ldg((const float4*)xr);
        float4 xb = __ldg((const float4*)(xr + 4));
        uint2 fw = __ldg((const uint2*)(fb + (h0 + j) * SPB));
        float4 fa = dec4(fw.x);
        float4 fb4 = dec4(fw.y);
        accum4(xa, fa, uA, vA);
        accum4(xb, fb4, uB, vB);
        if (j == 2) { rcA[0] = xa; rcB[0] = xb; }   // row h0   -> slot 0
        if (j == 3) { rcA[1] = xa; rcB[1] = xb; }   // row h0+1 -> slot 1
    }

    float acc0 = 0.f, acc1 = 0.f;

#pragma unroll 1
    for (int gg = 0; gg < HROWS / 2; gg++) {
#pragma unroll
        for (int kk = 0; kk < 2; kk++) {
            const int r = h0 + gg * 2 + kk;       // r & 1 == kk
            int ri = r + 2 > 255 ? 255 : r + 2;
            // incoming row r+2 (x DRAM stream, fv plane row r+4, iv row r+2)
            const float* xri = xp + (ri << 8);
            float4 xiA = __ldg((const float4*)xri);
            float4 xiB = __ldg((const float4*)(xri + 4));
            uint2 fwi = __ldg((const uint2*)(fb + (r + 4) * SPB));
            uint2 fwd = __ldg((const uint2*)(fb + r * SPB));
            const float4* pir = pi + (r + 2) * SPF4;
            float4 ivA = __ldg(pir);
            float4 ivB = __ldg(pir + 1);

            float4 fiA = dec4(fwi.x);
            float4 fiB = dec4(fwi.y);
            accum4(xiA, fiA, uA, vA);
            accum4(xiB, fiB, uB, vB);

            // halo via 8 shuffles; image-boundary halos zeroed
            float eul0 = __shfl_up_sync(FULLMASK, uB.z, 1);
            float eul1 = __shfl_up_sync(FULLMASK, uB.w, 1);
            float evl0 = __shfl_up_sync(FULLMASK, vB.z, 1);
            float evl1 = __shfl_up_sync(FULLMASK, vB.w, 1);
            float eur0 = __shfl_down_sync(FULLMASK, uA.x, 1);
            float eur1 = __shfl_down_sync(FULLMASK, uA.y, 1);
            float evr0 = __shfl_down_sync(FULLMASK, vA.x, 1);
            float evr1 = __shfl_down_sync(FULLMASK, vA.y, 1);
            if (lane == 0) { eul0 = 0.f; eul1 = 0.f; evl0 = 0.f; evl1 = 0.f; }
            if (lane == 31) { eur0 = 0.f; eur1 = 0.f; evr0 = 0.f; evr1 = 0.f; }

            float U[8], V[8];
            win8(eul0, eul1, uA, uB, eur0, eur1, U);
            win8(evl0, evl1, vA, vB, evr0, evr1, V);

            // departing row r-2: x reloaded (L1-hot), fv plane row r
            int rd = r - 2 < 0 ? 0 : r - 2;
            const float* xrd = xp + (rd << 8);
            float4 xdA = __ldg((const float4*)xrd);
            float4 xdB = __ldg((const float4*)(xrd + 4));
            float4 fdA = dec4(fwd.x);
            float4 fdB = dec4(fwd.y);
            decum4(xdA, fdA, uA, vA);
            decum4(xdB, fdB, uB, vB);

            // epilogue: center row r (x from parity ring)
            epi(ivA.x, U[0], V[0], rcA[kk].x, acc0, acc1);
            epi(ivA.y, U[1], V[1], rcA[kk].y, acc0, acc1);
            epi(ivA.z, U[2], V[2], rcA[kk].z, acc0, acc1);
            epi(ivA.w, U[3], V[3], rcA[kk].w, acc0, acc1);
            epi(ivB.x, U[4], V[4], rcB[kk].x, acc0, acc1);
            epi(ivB.y, U[5], V[5], rcB[kk].y, acc0, acc1);
            epi(ivB.z, U[6], V[6], rcB[kk].z, acc0, acc1);
            epi(ivB.w, U[7], V[7], rcB[kk].w, acc0, acc1);

            // push incoming row r+2 into slot (r+2)&1 == kk
            rcA[kk] = xiA;
            rcB[kk] = xiB;
        }
    }

    // warp reduce + block reduce -> 2 double atomics per block
#pragma unroll
    for (int o = 16; o; o >>= 1) {
        acc0 += __shfl_xor_sync(FULLMASK, acc0, o);
        acc1 += __shfl_xor_sync(FULLMASK, acc1, o);
    }
    if (lane == 0) { sred[0][wid] = (double)acc0; sred[1][wid] = (double)acc1; }
    __syncthreads();
    if (threadIdx.x == 0) {
        double t0 = 0.0, t1 = 0.0;
#pragma unroll
        for (int i = 0; i < 8; i++) { t0 += sred[0][i]; t1 += sred[1][i]; }
        atomicAdd(&g_loss[0], t0);
        atomicAdd(&g_loss[1], t1);
    }
}

// ---------------- Kernel D: finalize ---------------------------------------
__global__ void kernD(float* out) {
    double total = 0.0;
    int ncls = 0;
#pragma unroll
    for (int c = 0; c < 2; c++) {
        bool valid = (g_cal[c] >= 1) && (g_nsel[c] >= 1);
        double denom = (double)g_nsel[c] * 256.0;
        if (denom < 1.0) denom = 1.0;
        double lc = g_loss[c] / denom;
        if (valid) { total += lc; ncls++; }
    }
    out[0] = (ncls == 0) ? 0.0f : (float)(total / (double)ncls);
}

extern "C" void kernel_launch(void* const* d_in, const int* in_sizes, int n_in,
                              void* d_out, int out_size) {
    const float* xfeat = (const float*)d_in[0];   // [4,256,256,256] f32
    const float* clf   = (const float*)d_in[1];   // [4,2,256,256]   f32
    const int*   gt    = (const int*)d_in[2];     // [4,256,256]     i32
    float* out = (float*)d_out;

    kernA<<<NPIX / 256, 256>>>(gt, clf);
    kernB<<<NPIX / 256, 256>>>();
    kernC<<<NBLKC, 256>>>(xfeat);
    kernD<<<1, 1>>>(out);
}

// round 15
// speedup vs baseline: 1.2600x; 1.2600x over previous
#include <cuda_runtime.h>

#define BB 4
#define CC 256
#define HH 256
#define WW 256
#define HWSZ (HH * WW)
#define NPIX (BB * HWSZ)
#define FULLMASK 0xFFFFFFFFu

#define NBLK 592
#define NTHR 256
#define NTH_TOT (NBLK * NTHR)          // 151552 threads
#define NWARP (NBLK * 8)               // 4736 warps
#define NTASK (5 * 9 * 4 * 256)        // 46080 warp-tasks
#define PROWS 274                      // rows 0,1 + 2..257 data + 258..273 zero
#define PPITCH 128                     // float2 per plane row
#define PLSZ (PROWS * PPITCH)
#define ZROW 258                       // first guaranteed-zero bottom pad row

typedef unsigned long long ull;
// packed f32x2 ops (sm_103a FFMA2 path; ptxas won't emit these from C++)
__device__ __forceinline__ ull fmul2(ull a, ull b) {
    ull r; asm("mul.rn.f32x2 %0, %1, %2;" : "=l"(r) : "l"(a), "l"(b)); return r;
}
__device__ __forceinline__ ull fadd2(ull a, ull b) {
    ull r; asm("add.rn.f32x2 %0, %1, %2;" : "=l"(r) : "l"(a), "l"(b)); return r;
}
__device__ __forceinline__ ull ffma2(ull a, ull b, ull c) {
    ull r; asm("fma.rn.f32x2 %0, %1, %2, %3;" : "=l"(r) : "l"(a), "l"(b), "l"(c)); return r;
}
#define NEG1X2 0xBF800000BF800000ULL   // (-1.0f, -1.0f)

// intermediates
__device__ unsigned char g_info[NPIX];
// fv plane: image row h stored at plane row h+2; fv = +-1 if correct (sign=class) else 0
__device__ float2 g_fvp[BB * PLSZ];
// iv plane: image row h stored at plane row h+2; iv = +-1/(cnt+1e-5) if mse-masked else 0
__device__ float2 g_ivp[BB * PLSZ];
__device__ double g_loss[2];
__device__ int g_nsel[2], g_cal[2];
__device__ int g_task;
__device__ int g_bar_count = 0;
__device__ volatile int g_bar_gen = 0;

__device__ __forceinline__ void gridsync() {
    __syncthreads();
    if (threadIdx.x == 0) {
        __threadfence();
        int gen = g_bar_gen;
        if (atomicAdd(&g_bar_count, 1) == NBLK - 1) {
            g_bar_count = 0;
            __threadfence();
            g_bar_gen = gen + 1;
        } else {
            while (g_bar_gen == gen) { __nanosleep(64); }
        }
        __threadfence();
    }
    __syncthreads();
}

__global__ void __launch_bounds__(NTHR, 4) kernFused(
    const float* __restrict__ x, const float* __restrict__ clf,
    const int* __restrict__ gt, float* __restrict__ out) {
    __shared__ double sred[2][8];
    const int tid0 = blockIdx.x * NTHR + threadIdx.x;

    // ================= Phase 1a: per-pixel info + plane pad zeroing =========
    for (int i = tid0; i < BB * 18 * WW; i += NTH_TOT) {
        int col = i & 255;
        int j = (i >> 8) % 18;
        int b = (i >> 8) / 18;
        int row = (j < 2) ? j : (j + 256);      // rows 0,1,258..273
        ((float*)(g_fvp + (size_t)b * PLSZ))[row * WW + col] = 0.f;
        ((float*)(g_ivp + (size_t)b * PLSZ))[row * WW + col] = 0.f;
    }
    for (int p = tid0; p < NPIX; p += NTH_TOT) {
        if (p == 0) {
            g_loss[0] = 0.0; g_loss[1] = 0.0;
            g_nsel[0] = 0; g_nsel[1] = 0;
            g_cal[0] = 0; g_cal[1] = 0;
            g_task = 0;
        }
        int b = p >> 16;
        int hw = p & (HWSZ - 1);
        int h = hw >> 8;
        int w = hw & (WW - 1);
        int g = gt[p];
        float c0 = clf[(size_t)(b * 2) * HWSZ + hw];
        float c1 = clf[(size_t)(b * 2 + 1) * HWSZ + hw];
        int pred = (c1 > c0) ? 1 : 0;          // argmax ties -> index 0
        int correct = (pred == g) ? 1 : 0;
        int edge = (g == -1) ? 1 : 0;
        if (h < HH - 5) edge |= (gt[p + 5 * WW] != g) ? 1 : 0;
        if (w < WW - 5) edge |= (gt[p + 5] != g) ? 1 : 0;
        g_info[p] = (unsigned char)((g & 1) | (correct << 1) | (edge << 2));
    }
    gridsync();

    // ================= Phase 1b: ring counts -> fv/iv planes + counters =====
    for (int p = tid0; p < NPIX; p += NTH_TOT) {
        int b = p >> 16;
        int hw = p & (HWSZ - 1);
        int h = hw >> 8;
        int w = hw & (WW - 1);
        unsigned info = g_info[p];
        int g = info & 1;
        int correct = (info >> 1) & 1;
        int edge = (info >> 2) & 1;
        int cntCorr = 0, cntCls = 0;
#pragma unroll
        for (int dh = -2; dh <= 2; dh++) {
#pragma unroll
            for (int dw = -2; dw <= 2; dw++) {
                if (dh == 0 && dw == 0) continue;
                int hh = h + dh, wp = w + dw;
                if ((unsigned)hh < HH && (unsigned)wp < WW) {
                    unsigned qi = g_info[p + dh * WW + dw];
                    int same = ((int)(qi & 1) == g) ? 1 : 0;
                    cntCls += same;
                    cntCorr += same & (int)((qi >> 1) & 1);
                }
            }
        }
        int mse = correct & edge & (cntCorr >= 1 ? 1 : 0);
        int cal = edge & (cntCls >= 1 ? 1 : 0);

        float fv = correct ? (g ? 1.0f : -1.0f) : 0.0f;
        float inv = 1.0f / ((float)cntCorr + 1e-5f);
        float ivs = mse ? (g ? inv : -inv) : 0.0f;

        ((float*)(g_fvp + (size_t)b * PLSZ))[(h + 2) * WW + w] = fv;
        ((float*)(g_ivp + (size_t)b * PLSZ))[(h + 2) * WW + w] = ivs;

        unsigned bm;
        bm = __ballot_sync(FULLMASK, mse && g == 0);
        if ((threadIdx.x & 31) == 0 && bm) atomicAdd(&g_nsel[0], __popc(bm));
        bm = __ballot_sync(FULLMASK, mse && g == 1);
        if ((threadIdx.x & 31) == 0 && bm) atomicAdd(&g_nsel[1], __popc(bm));
        bm = __ballot_sync(FULLMASK, cal && g == 0);
        if ((threadIdx.x & 31) == 0 && bm) atomicAdd(&g_cal[0], __popc(bm));
        bm = __ballot_sync(FULLMASK, cal && g == 1);
        if ((threadIdx.x & 31) == 0 && bm) atomicAdd(&g_cal[1], __popc(bm));
    }
    gridsync();

    // ================= Phase 2: separable 2-class box filter ================
    // Identical geometry to the 133.6us champion (span-2, 5 wbands x 9 hbands,
    // parked pointers, 5-row groups, ring-5), with: (a) atomic work stealing,
    // (b) packed f32x2 math for ring products and u/v slide.
    const int lane = threadIdx.x & 31;
    const int wid = threadIdx.x >> 5;
    float acc0 = 0.f, acc1 = 0.f;

    for (;;) {
        int t;
        if (lane == 0) t = atomicAdd(&g_task, 1);
        t = __shfl_sync(FULLMASK, t, 0);
        if (t >= NTASK) break;

        int wband = t % 5;
        int r1 = t / 5;
        int hband = r1 % 9;
        int r2 = r1 / 9;
        int b = r2 & 3;
        int ch = r2 >> 2;
        int h0 = hband * 30;
        int wl = wband * 60 - 2 + (lane << 1);
        bool colv = (wl >= 0) && (wl <= 254);
        bool qv = colv && (lane >= 1) && (lane <= 30);
        int wc = colv ? wl : (wl < 0 ? 0 : 254);
        int pc = wc >> 1;                       // float2 col in planes

        const float* xc = x + ((size_t)(b * CC + ch) << 16) + wc;
        const float2* plb = g_fvp + (size_t)b * PLSZ;
        const float2* ilb = g_ivp + (size_t)b * PLSZ;
        // main-loop plane pointers: park invalid lanes on a zero row, stride 0
        const float2* fvp = colv ? (plb + (h0 + 4) * PPITCH + pc) : (plb + ZROW * PPITCH);
        const float2* ivp = qv ? (ilb + (h0 + 2) * PPITCH + pc) : (ilb + ZROW * PPITCH);
        const int fstep = colv ? 5 * PPITCH : 0;
        const int istep = qv ? 5 * PPITCH : 0;

        ull pt[5], ps[5];                      // packed (x,y) products
        ull u = 0ULL, v = 0ULL;

        // prologue rows h0-2..h0+1 -> ring slots 0..3 (fv plane rows h0..h0+3)
        const float2* fvpro = colv ? (plb + h0 * PPITCH + pc) : (plb + ZROW * PPITCH);
#pragma unroll
        for (int k = 0; k < 4; k++) {
            int r = h0 - 2 + k;
            int rc = r < 0 ? 0 : r;
            float2 xvf = __ldg((const float2*)(xc + (rc << 8)));
            float2 fvf = __ldg(fvpro + k * PPITCH);
            ull X = *(ull*)&xvf;
            ull F = *(ull*)&fvf;
            ull S = fmul2(X, F);               // x*f
            ull T = fmul2(S, F);               // x*f^2 = x*|f|
            pt[k] = T; ps[k] = S;
            u = fadd2(u, T);
            v = fadd2(v, S);
        }
        pt[4] = 0ULL;
        ps[4] = 0ULL;

#pragma unroll 1
        for (int g = 0; g < 6; g++) {
            const int rbase = h0 + 2 + g * 5;
            // batch-prefetch the 5 DRAM x rows (MLP 5)
            float2 xn[5];
#pragma unroll
            for (int k = 0; k < 5; k++) {
                int r = rbase + k;
                int rc = r > 255 ? 255 : r;
                xn[k] = __ldg((const float2*)(xc + (rc << 8)));
            }
#pragma unroll
            for (int k = 0; k < 5; k++) {
                const int sn = (k + 4) % 5;    // departing slot
                const int sc = (k + 2) % 5;    // center-row slot
                // L2-resident plane loads, immediate offsets
                float2 fvf = __ldg(fvp + k * PPITCH);
                float2 iv = __ldg(ivp + k * PPITCH);
                // slide out departing row (packed fma with -1)
                u = ffma2(pt[sn], NEG1X2, u);
                v = ffma2(ps[sn], NEG1X2, v);
                // slide in incoming row
                ull X = *(ull*)&xn[k];
                ull F = *(ull*)&fvf;
                ull S = fmul2(X, F);
                ull T = fmul2(S, F);
                pt[sn] = T; ps[sn] = S;
                u = fadd2(u, T);
                v = fadd2(v, S);
                // horizontal halo via shuffles
                float2 uf = *(float2*)&u;
                float2 vf = *(float2*)&v;
                float ulx = __shfl_up_sync(FULLMASK, uf.x, 1);
                float uly = __shfl_up_sync(FULLMASK, uf.y, 1);
                float urx = __shfl_down_sync(FULLMASK, uf.x, 1);
                float ury = __shfl_down_sync(FULLMASK, uf.y, 1);
                float vlx = __shfl_up_sync(FULLMASK, vf.x, 1);
                float vly = __shfl_up_sync(FULLMASK, vf.y, 1);
                float vrx = __shfl_down_sync(FULLMASK, vf.x, 1);
                float vry = __shfl_down_sync(FULLMASK, vf.y, 1);
                float cu = uly + uf.x + uf.y + urx;
                float cw = vly + vf.x + vf.y + vrx;
                float u50 = ulx + cu, u51 = cu + ury;
                float v50 = vlx + cw, v51 = cw + vry;
                // epilogue; class = sign(iv), zero iv -> no accumulation
                float s20 = iv.x, s21 = iv.y;
                float2 cen = *(float2*)&pt[sc];    // = x at masked px
                float a0 = fabsf(s20), a1 = fabsf(s21);
                float t10 = fmaf(0.5f, u50, -cen.x);
                float t11 = fmaf(0.5f, u51, -cen.y);
                float dd0 = fmaf(-0.5f * s20, v50, fmaf(-t10, a0, cen.x));
                float dd1 = fmaf(-0.5f * s21, v51, fmaf(-t11, a1, cen.y));
                float q0 = dd0 * dd0, q1 = dd1 * dd1;
                if (s20 > 0.f) acc1 += q0; else if (s20 < 0.f) acc0 += q0;
                if (s21 > 0.f) acc1 += q1; else if (s21 < 0.f) acc0 += q1;
            }
            fvp += fstep;
            ivp += istep;
        }
    }

    // block reduction -> 2 double atomics per block
#pragma unroll
    for (int o = 16; o; o >>= 1) {
        acc0 += __shfl_xor_sync(FULLMASK, acc0, o);
        acc1 += __shfl_xor_sync(FULLMASK, acc1, o);
    }
    if (lane == 0) { sred[0][wid] = (double)acc0; sred[1][wid] = (double)acc1; }
    __syncthreads();
    if (threadIdx.x == 0) {
        double t0 = 0.0, t1 = 0.0;
#pragma unroll
        for (int i = 0; i < 8; i++) { t0 += sred[0][i]; t1 += sred[1][i]; }
        atomicAdd(&g_loss[0], t0);
        atomicAdd(&g_loss[1], t1);
    }
    gridsync();

    // ================= Phase 3: finalize =====================================
    if (blockIdx.x == 0 && threadIdx.x == 0) {
        double total = 0.0;
        int ncls = 0;
#pragma unroll
        for (int c = 0; c < 2; c++) {
            int ns = *(volatile int*)&g_nsel[c];
            int ca = *(volatile int*)&g_cal[c];
            double ls = *(volatile double*)&g_loss[c];
            bool valid = (ca >= 1) && (ns >= 1);
            double denom = (double)ns * 256.0;
            if (denom < 1.0) denom = 1.0;
            if (valid) { total += ls / denom; ncls++; }
        }
        out[0] = (ncls == 0) ? 0.0f : (float)(total / (double)ncls);
    }
}

extern "C" void kernel_launch(void* const* d_in, const int* in_sizes, int n_in,
                              void* d_out, int out_size) {
    const float* xfeat = (const float*)d_in[0];   // [4,256,256,256] f32
    const float* clf   = (const float*)d_in[1];   // [4,2,256,256]   f32
    const int*   gt    = (const int*)d_in[2];     // [4,256,256]     i32
    float* out = (float*)d_out;

    kernFused<<<NBLK, NTHR>>>(xfeat, clf, gt, out);
}